// round 13
// baseline (speedup 1.0000x reference)
#include <cuda_runtime.h>
#include <cuda_fp16.h>
#include <stdint.h>
#include <math.h>

#define Bn 128
#define Ln 1024
#define Vn 32
#define En 256
#define Hn 1024
#define NTOT 1056        // Hn + Vn (W_o folded)

#define NG  4            // independent batch groups
#define BG  32           // batch rows per group
#define NTL 33           // CTAs per group (32 h-tiles + 1 logits tile)
#define NSL 32           // N cols per CTA
#define G   (NG * NTL)   // 132 persistent CTAs
#define NT  256          // 8 warps (one per k-slice)
#define KW  128          // K columns per warp
#define PA  1032         // A/B smem pitch (fp16): 2064B stride -> LDSM conflict-free
#define PN  36           // reduction pitch (floats)

// ---------------- device scratch ----------------
__device__ float    g_P[Vn * Hn];
__device__ __half   g_hf[2][Bn * Hn];       // fp16 hidden (single buffer per parity)
__device__ __half   g_WT_hi[NTOT * Hn];     // [n][k] fp16 hi
__device__ __half   g_WT_lo[NTOT * Hn];     // fp16 residual
__device__ unsigned g_cnt_all;              // prologue barrier (all G)
__device__ unsigned g_cntg[NG * 32];        // 4 sub-counters per group, 32B padded

// smem layout (bytes):
//  sA   : 0       .. 66048   (32 x PA fp16)  [setup: B-hi staging]
//  (setup only) B-lo staging at 66048 .. 132096
//  sRed : 66048   .. 102912  (8 x 32 x PN floats)   [steady state]
//  sX   : 102912  .. 103040
#define OFF_ALO 66048
#define OFF_RED 66048
#define OFF_X   102912
#define SMEM_BYTES 132096
#define A_MT (16 * PA * 2)   // byte offset between m-tiles

// ---------------- helpers ----------------
#define MMAF16(d, a0, a1, a2, a3, b0, b1) \
    asm volatile("mma.sync.aligned.m16n8k16.row.col.f32.f16.f16.f32 " \
        "{%0,%1,%2,%3}, {%4,%5,%6,%7}, {%8,%9}, {%0,%1,%2,%3};" \
        : "+f"((d)[0]), "+f"((d)[1]), "+f"((d)[2]), "+f"((d)[3]) \
        : "r"(a0), "r"(a1), "r"(a2), "r"(a3), "r"(b0), "r"(b1))

#define LDSM4(r0, r1, r2, r3, addr) \
    asm volatile("ldmatrix.sync.aligned.m8n8.x4.shared.b16 {%0,%1,%2,%3}, [%4];" \
        : "=r"(r0), "=r"(r1), "=r"(r2), "=r"(r3) : "r"(addr))

__device__ __forceinline__ uint32_t smem_u32(const void* p) {
    uint32_t a;
    asm("{ .reg .u64 t; cvta.to.shared.u64 t, %1; cvt.u32.u64 %0, t; }"
        : "=r"(a) : "l"(p));
    return a;
}
__device__ __forceinline__ unsigned acqload(const unsigned* p) {
    unsigned v;
    asm volatile("ld.acquire.gpu.u32 %0, [%1];" : "=r"(v) : "l"(p) : "memory");
    return v;
}
__device__ __forceinline__ void arrive(unsigned* cnt) {
    asm volatile("red.release.gpu.global.add.u32 [%0], 1;" :: "l"(cnt) : "memory");
}
__device__ __forceinline__ void waitcnt(unsigned* cnt, unsigned target) {
    unsigned v = acqload(cnt);
    while ((int)(v - target) < 0) v = acqload(cnt);
}
__device__ __forceinline__ uint4 ldcg4(const void* p) {
    uint4 r;
    asm volatile("ld.global.cg.v4.u32 {%0,%1,%2,%3}, [%4];"
        : "=r"(r.x), "=r"(r.y), "=r"(r.z), "=r"(r.w) : "l"(p));
    return r;
}
__device__ __forceinline__ void pack_h16(float v, unsigned short& hi, unsigned short& lo) {
    __half hb = __float2half_rn(v);
    hi = __half_as_ushort(hb);
    lo = __half_as_ushort(__float2half_rn(v - __half2float(hb)));
}
__device__ __forceinline__ float fast_tanh(float x) {
    float e = __expf(2.0f * x);
    return 1.0f - __fdividef(2.0f, e + 1.0f);
}

// ---------------- the single persistent kernel ----------------
__global__ void __launch_bounds__(NT, 1)
rnn_all(const int* __restrict__ x, const float* __restrict__ hidden,
        const float* __restrict__ emb, const float* __restrict__ We,
        const float* __restrict__ Wh, const float* __restrict__ bh,
        const float* __restrict__ Wo, const float* __restrict__ bo,
        float* __restrict__ logits, float* __restrict__ outh) {
    extern __shared__ __align__(16) char dsm[];
    __half* sA   = (__half*)dsm;
    float*  sRed = (float*)(dsm + OFF_RED);
    int*    sX   = (int*)(dsm + OFF_X);

    const int tid = threadIdx.x, bid = blockIdx.x;
    const int g     = bid / NTL;        // batch group 0..3
    const int ntl   = bid % NTL;        // 0..32 (32 = logits tile)
    const int gbase = g * BG;
    const int ncol0 = ntl * NSL;        // global N col base (1024 = logits)
    const int lane = tid & 31, w = tid >> 5;
    const int gq = lane >> 2, tg = lane & 3;
    const int kw = w * KW;              // this warp's k-slice base

    unsigned tokA = acqload(&g_cnt_all);
    // 4-way split barrier: thread s<4 tracks sub-counter s
    unsigned tokSub = 0;
    if (tid < 4) tokSub = acqload(&g_cntg[g * 32 + tid * 8]);
    const unsigned subCnt = (tid == 0) ? 9u : 8u;   // ntl&3 == 0 has 9 members

    // ======== prologue ========
    for (int k2 = tid; k2 < Hn; k2 += NT) {
#pragma unroll
        for (int j = 0; j < 8; ++j) {
            int n = bid * 8 + j;
            float wv = (n < Hn) ? Wh[k2 * Hn + n] : Wo[k2 * Vn + (n - Hn)];
            unsigned short hi, lo; pack_h16(wv, hi, lo);
            g_WT_hi[n * Hn + k2] = __ushort_as_half(hi);
            g_WT_lo[n * Hn + k2] = __ushort_as_half(lo);
        }
    }
    {
        int e = bid * NT + tid;
        if (e < Vn * Hn) {
            int v = e >> 10, h = e & 1023;
            float acc = bh[h];
            const float* er = emb + v * En;
#pragma unroll 8
            for (int q = 0; q < En; ++q) acc = fmaf(er[q], We[q * Hn + h], acc);
            g_P[e] = acc;
        }
    }
    if (bid < Bn) {
        int i0 = bid * Hn + tid * 4;
        float4 hv = *(const float4*)(hidden + i0);
        float vv[4] = {hv.x, hv.y, hv.z, hv.w};
        unsigned short uh[4], ul[4];
#pragma unroll
        for (int j = 0; j < 4; ++j) pack_h16(vv[j], uh[j], ul[j]);
        *(uint2*)(&g_hf[0][i0]) = make_uint2(uh[0] | (uh[1] << 16), uh[2] | (uh[3] << 16));
    }
    __syncthreads();
    if (tid == 0) arrive(&g_cnt_all);
    tokA += G;
    if (tid == 0) waitcnt(&g_cnt_all, tokA);
    __syncthreads();

    // ======== B setup: stage hi/lo tiles once, LDSM fragments into registers ========
    uint32_t Bh[8][4][2], Bl[8][4][2];
    {
        __half* sBlo = (__half*)(dsm + OFF_ALO);
#pragma unroll
        for (int it = 0; it < 16; ++it) {
            int i = (it * NT + tid) * 8;
            int n = i >> 10, k = i & 1023;
            *(uint4*)(sA + n * PA + k)   = *(const uint4*)(&g_WT_hi[(ncol0 + n) * Hn + k]);
            *(uint4*)(sBlo + n * PA + k) = *(const uint4*)(&g_WT_lo[(ncol0 + n) * Hn + k]);
        }
        __syncthreads();
        const uint32_t bBase = smem_u32(sA) +
            (uint32_t)(2 * ((lane & 7) * PA + kw + ((lane >> 3) & 1) * 8));
#pragma unroll
        for (int nb2 = 0; nb2 < 2; ++nb2) {
            const uint32_t ba = bBase + (uint32_t)(2 * (nb2 * 2 + (lane >> 4)) * 8 * PA);
#pragma unroll
            for (int ks = 0; ks < 8; ++ks) {
                LDSM4(Bh[ks][nb2 * 2][0], Bh[ks][nb2 * 2][1],
                      Bh[ks][nb2 * 2 + 1][0], Bh[ks][nb2 * 2 + 1][1], ba + ks * 32);
                LDSM4(Bl[ks][nb2 * 2][0], Bl[ks][nb2 * 2][1],
                      Bl[ks][nb2 * 2 + 1][0], Bl[ks][nb2 * 2 + 1][1],
                      ba + ks * 32 + (uint32_t)OFF_ALO);
            }
        }
        __syncthreads();
    }

    // A fragment base (this warp's k-slice)
    const uint32_t aAddr = smem_u32(sA) +
        (uint32_t)(2 * (((lane & 7) + ((lane >> 3) & 1) * 8) * PA + kw + (lane >> 4) * 8));

    // ======== recurrence ========
    for (int l = 0; l <= Ln; ++l) {
        const int c = l & 1;
        const bool act = (l < Ln) || (ntl == NTL - 1);

        if (act) {   // stage A: 32 rows x 1024 k fp16, L2-only loads
#pragma unroll
            for (int it = 0; it < 16; ++it) {
                int i = (it * NT + tid) * 8;
                int row = i >> 10, k = i & 1023;
                *(uint4*)(sA + row * PA + k) = ldcg4(&g_hf[c][(gbase + row) * Hn + k]);
            }
        }
        if (l < Ln && tid < BG) sX[tid] = __ldg(&x[(gbase + tid) * Ln + l]);
        __syncthreads();

        if (act) {
            float acc[2][4][4];
#pragma unroll
            for (int mt = 0; mt < 2; ++mt)
#pragma unroll
                for (int nb = 0; nb < 4; ++nb)
#pragma unroll
                    for (int q = 0; q < 4; ++q) acc[mt][nb][q] = 0.f;

#pragma unroll
            for (int mt = 0; mt < 2; ++mt) {
                const uint32_t mo = (uint32_t)(mt * A_MT);
#pragma unroll
                for (int ks = 0; ks < 8; ++ks) {
                    uint32_t a0, a1, a2, a3;
                    LDSM4(a0, a1, a2, a3, aAddr + mo + ks * 32);
#pragma unroll
                    for (int nb = 0; nb < 4; ++nb) {
                        MMAF16(acc[mt][nb], a0, a1, a2, a3, Bh[ks][nb][0], Bh[ks][nb][1]);
                        MMAF16(acc[mt][nb], a0, a1, a2, a3, Bl[ks][nb][0], Bl[ks][nb][1]);
                    }
                }
            }
            // per-warp partials (k-slice sums) -> smem
            float* rp = sRed + w * 32 * PN;
#pragma unroll
            for (int mt = 0; mt < 2; ++mt)
#pragma unroll
                for (int nb = 0; nb < 4; ++nb) {
                    int r0 = mt * 16 + gq, col = nb * 8 + tg * 2;
                    *(float2*)(rp + r0 * PN + col)       = make_float2(acc[mt][nb][0], acc[mt][nb][1]);
                    *(float2*)(rp + (r0 + 8) * PN + col) = make_float2(acc[mt][nb][2], acc[mt][nb][3]);
                }
        }
        __syncthreads();

        if (act) {
            // reduce 8 k-slices: thread owns row m, cols n0..n0+3
            const int m = tid >> 3, n0 = (tid & 7) * 4;
            float4 s = *(const float4*)(sRed + m * PN + n0);
#pragma unroll
            for (int j = 1; j < 8; ++j) {
                float4 p = *(const float4*)(sRed + j * 32 * PN + m * PN + n0);
                s.x += p.x; s.y += p.y; s.z += p.z; s.w += p.w;
            }
            if (ntl < NTL - 1) {
                if (l < Ln) {
                    const int xv = sX[m];
                    float4 Pv = *(const float4*)(&g_P[xv * Hn + ncol0 + n0]);
                    float h0 = fast_tanh(s.x + Pv.x), h1 = fast_tanh(s.y + Pv.y);
                    float h2 = fast_tanh(s.z + Pv.z), h3 = fast_tanh(s.w + Pv.w);
                    unsigned short u0 = __half_as_ushort(__float2half_rn(h0));
                    unsigned short u1 = __half_as_ushort(__float2half_rn(h1));
                    unsigned short u2 = __half_as_ushort(__float2half_rn(h2));
                    unsigned short u3 = __half_as_ushort(__float2half_rn(h3));
                    int i0 = (gbase + m) * Hn + ncol0 + n0;
                    *(uint2*)(&g_hf[1 - c][i0]) =
                        make_uint2(u0 | (u1 << 16), u2 | (u3 << 16));
                    if (l == Ln - 1)
                        *(float4*)(&outh[i0]) = make_float4(h0, h1, h2, h3);
                }
            } else if (l > 0) {
                float4 B0 = *(const float4*)(&bo[n0]);
                *(float4*)(&logits[((size_t)(gbase + m) * Ln + (l - 1)) * Vn + n0]) =
                    make_float4(s.x + B0.x, s.y + B0.y, s.z + B0.z, s.w + B0.w);
            }
        }

        // per-group barrier (1 per step, 4-way split arrivals)
        if (l < Ln) {
            __syncthreads();
            if (tid == 0) arrive(&g_cntg[g * 32 + (ntl & 3) * 8]);
            if (tid < 4) {
                tokSub += subCnt;
                waitcnt(&g_cntg[g * 32 + tid * 8], tokSub);
            }
            __syncthreads();
        }
    }
}

extern "C" void kernel_launch(void* const* d_in, const int* in_sizes, int n_in,
                              void* d_out, int out_size) {
    const int*   x      = (const int*)d_in[0];
    const float* hidden = (const float*)d_in[1];
    const float* emb    = (const float*)d_in[2];
    const float* We     = (const float*)d_in[3];
    const float* Wh     = (const float*)d_in[4];
    const float* bh     = (const float*)d_in[5];
    const float* Wo     = (const float*)d_in[6];
    const float* bo     = (const float*)d_in[7];

    float* logits = (float*)d_out;
    float* outh   = logits + (size_t)Bn * Ln * Vn;

    cudaFuncSetAttribute(rnn_all,
                         cudaFuncAttributeMaxDynamicSharedMemorySize, SMEM_BYTES);
    rnn_all<<<G, NT, SMEM_BYTES>>>(x, hidden, emb, We, Wh, bh, Wo, bo, logits, outh);
}

// round 14
// speedup vs baseline: 1.2123x; 1.2123x over previous
#include <cuda_runtime.h>
#include <cuda_fp16.h>
#include <stdint.h>
#include <math.h>

#define Bn 128
#define Ln 1024
#define Vn 32
#define En 256
#define Hn 1024
#define NTOT 1056        // Hn + Vn (W_o folded)

#define NG  4            // independent batch groups
#define BG  32           // batch rows per group
#define NTL 33           // CTAs per group (32 h-producers + 1 logits tile)
#define NSL 32           // N cols per CTA
#define G   (NG * NTL)   // 132 persistent CTAs
#define NT  256          // 8 warps (one per k-slice)
#define KW  128          // K columns per warp
#define PA  1032         // A/B smem pitch (fp16): 2064B stride -> LDSM conflict-free
#define PN  36           // reduction pitch (floats)

// ---------------- device scratch ----------------
__device__ float    g_P[Vn * Hn];
__device__ __half   g_hf[2][Bn * Hn];       // fp16 hidden, double-buffered
__device__ __half   g_WT_hi[NTOT * Hn];     // [n][k] fp16 hi
__device__ __half   g_WT_lo[NTOT * Hn];     // fp16 residual
__device__ unsigned g_cnt_all;              // prologue barrier (all G)
__device__ unsigned g_flag[NG][32 * 8];     // per-producer step flags (32B padded)
__device__ unsigned g_flagL[NG * 8];        // logits-CTA read-done flags

// smem layout (bytes)
#define OFF_BLO 66048                       // (setup only) B-lo staging
#define OFF_RED 66048                       // steady state: reduction buffer
#define OFF_X   102912
#define SMEM_BYTES 132096
#define A_MT (16 * PA * 2)                  // byte offset between m-tiles

// ---------------- helpers ----------------
#define MMAF16(d, a0, a1, a2, a3, b0, b1) \
    asm volatile("mma.sync.aligned.m16n8k16.row.col.f32.f16.f16.f32 " \
        "{%0,%1,%2,%3}, {%4,%5,%6,%7}, {%8,%9}, {%0,%1,%2,%3};" \
        : "+f"((d)[0]), "+f"((d)[1]), "+f"((d)[2]), "+f"((d)[3]) \
        : "r"(a0), "r"(a1), "r"(a2), "r"(a3), "r"(b0), "r"(b1))

#define LDSM4(r0, r1, r2, r3, addr) \
    asm volatile("ldmatrix.sync.aligned.m8n8.x4.shared.b16 {%0,%1,%2,%3}, [%4];" \
        : "=r"(r0), "=r"(r1), "=r"(r2), "=r"(r3) : "r"(addr))

__device__ __forceinline__ uint32_t smem_u32(const void* p) {
    uint32_t a;
    asm("{ .reg .u64 t; cvta.to.shared.u64 t, %1; cvt.u32.u64 %0, t; }"
        : "=r"(a) : "l"(p));
    return a;
}
__device__ __forceinline__ unsigned acqload(const unsigned* p) {
    unsigned v;
    asm volatile("ld.acquire.gpu.u32 %0, [%1];" : "=r"(v) : "l"(p) : "memory");
    return v;
}
__device__ __forceinline__ void relstore(unsigned* p, unsigned v) {
    asm volatile("st.release.gpu.u32 [%0], %1;" :: "l"(p), "r"(v) : "memory");
}
__device__ __forceinline__ void arrive(unsigned* cnt) {
    asm volatile("red.release.gpu.global.add.u32 [%0], 1;" :: "l"(cnt) : "memory");
}
__device__ __forceinline__ void waitcnt(unsigned* cnt, unsigned target) {
    unsigned v = acqload(cnt);
    while ((int)(v - target) < 0) v = acqload(cnt);
}
__device__ __forceinline__ uint4 ldcg4(const void* p) {
    uint4 r;
    asm volatile("ld.global.cg.v4.u32 {%0,%1,%2,%3}, [%4];"
        : "=r"(r.x), "=r"(r.y), "=r"(r.z), "=r"(r.w) : "l"(p));
    return r;
}
__device__ __forceinline__ void pack_h16(float v, unsigned short& hi, unsigned short& lo) {
    __half hb = __float2half_rn(v);
    hi = __half_as_ushort(hb);
    lo = __half_as_ushort(__float2half_rn(v - __half2float(hb)));
}
__device__ __forceinline__ float fast_tanh(float x) {
    float e = __expf(2.0f * x);
    return 1.0f - __fdividef(2.0f, e + 1.0f);
}

// ---------------- the single persistent kernel ----------------
__global__ void __launch_bounds__(NT, 1)
rnn_all(const int* __restrict__ x, const float* __restrict__ hidden,
        const float* __restrict__ emb, const float* __restrict__ We,
        const float* __restrict__ Wh, const float* __restrict__ bh,
        const float* __restrict__ Wo, const float* __restrict__ bo,
        float* __restrict__ logits, float* __restrict__ outh) {
    extern __shared__ __align__(16) char dsm[];
    __half* sA   = (__half*)dsm;
    float*  sRed = (float*)(dsm + OFF_RED);
    int*    sX   = (int*)(dsm + OFF_X);

    const int tid = threadIdx.x, bid = blockIdx.x;
    const int g     = bid / NTL;        // batch group 0..3
    const int ntl   = bid % NTL;        // 0..32 (32 = logits tile)
    const bool isProd = (ntl < NTL - 1);
    const int gbase = g * BG;
    const int ncol0 = ntl * NSL;        // global N col base (1024 = logits)
    const int lane = tid & 31, w = tid >> 5;
    const int gq = lane >> 2, tg = lane & 3;
    const int kw = w * KW;              // this warp's k-slice base

    unsigned tokA = acqload(&g_cnt_all);
    // flag bases (quiescent & self-consistent at launch)
    unsigned fb = 0;
    if (lane < 4) fb = acqload(&g_flag[g][(w * 4 + lane) * 8]);
    unsigned fbSelf = 0;
    if (tid == 0 && isProd) fbSelf = acqload(&g_flag[g][ntl * 8]);
    const unsigned fbL = acqload(&g_flagL[g * 8]);

    // ======== prologue ========
    for (int k2 = tid; k2 < Hn; k2 += NT) {
#pragma unroll
        for (int j = 0; j < 8; ++j) {
            int n = bid * 8 + j;
            float wv = (n < Hn) ? Wh[k2 * Hn + n] : Wo[k2 * Vn + (n - Hn)];
            unsigned short hi, lo; pack_h16(wv, hi, lo);
            g_WT_hi[n * Hn + k2] = __ushort_as_half(hi);
            g_WT_lo[n * Hn + k2] = __ushort_as_half(lo);
        }
    }
    {
        int e = bid * NT + tid;
        if (e < Vn * Hn) {
            int v = e >> 10, h = e & 1023;
            float acc = bh[h];
            const float* er = emb + v * En;
#pragma unroll 8
            for (int q = 0; q < En; ++q) acc = fmaf(er[q], We[q * Hn + h], acc);
            g_P[e] = acc;
        }
    }
    if (bid < Bn) {
        int i0 = bid * Hn + tid * 4;
        float4 hv = *(const float4*)(hidden + i0);
        float vv[4] = {hv.x, hv.y, hv.z, hv.w};
        unsigned short uh[4], ul[4];
#pragma unroll
        for (int j = 0; j < 4; ++j) pack_h16(vv[j], uh[j], ul[j]);
        *(uint2*)(&g_hf[0][i0]) = make_uint2(uh[0] | (uh[1] << 16), uh[2] | (uh[3] << 16));
    }
    __syncthreads();
    if (tid == 0) arrive(&g_cnt_all);
    tokA += G;
    if (tid == 0) waitcnt(&g_cnt_all, tokA);
    __syncthreads();

    // ======== B setup: stage hi/lo tiles once, LDSM fragments into registers ========
    uint32_t Bh[8][4][2], Bl[8][4][2];
    {
        __half* sBlo = (__half*)(dsm + OFF_BLO);
#pragma unroll
        for (int it = 0; it < 16; ++it) {
            int i = (it * NT + tid) * 8;
            int n = i >> 10, k = i & 1023;
            *(uint4*)(sA + n * PA + k)   = *(const uint4*)(&g_WT_hi[(ncol0 + n) * Hn + k]);
            *(uint4*)(sBlo + n * PA + k) = *(const uint4*)(&g_WT_lo[(ncol0 + n) * Hn + k]);
        }
        __syncthreads();
        const uint32_t bBase = smem_u32(sA) +
            (uint32_t)(2 * ((lane & 7) * PA + kw + ((lane >> 3) & 1) * 8));
#pragma unroll
        for (int nb2 = 0; nb2 < 2; ++nb2) {
            const uint32_t ba = bBase + (uint32_t)(2 * (nb2 * 2 + (lane >> 4)) * 8 * PA);
#pragma unroll
            for (int ks = 0; ks < 8; ++ks) {
                LDSM4(Bh[ks][nb2 * 2][0], Bh[ks][nb2 * 2][1],
                      Bh[ks][nb2 * 2 + 1][0], Bh[ks][nb2 * 2 + 1][1], ba + ks * 32);
                LDSM4(Bl[ks][nb2 * 2][0], Bl[ks][nb2 * 2][1],
                      Bl[ks][nb2 * 2 + 1][0], Bl[ks][nb2 * 2 + 1][1],
                      ba + ks * 32 + (uint32_t)OFF_BLO);
            }
        }
        __syncthreads();
    }

    // A fragment base (this warp's k-slice)
    const uint32_t aAddr = smem_u32(sA) +
        (uint32_t)(2 * (((lane & 7) + ((lane >> 3) & 1) * 8) * PA + kw + (lane >> 4) * 8));
    // staging decomposition: lane -> (row parity, 16B chunk)
    const int stRow = lane >> 4;           // 0..1
    const int stCh  = (lane & 15) * 8;     // 0..120

    // ======== recurrence (dataflow-synchronized) ========
    for (int l = 0; l <= Ln; ++l) {
        const int c = l & 1;
        const bool act = (l < Ln) || (!isProd);

        if (act) {
            // wait for this warp's 4 producers to have published h_l
            if (l > 0) {
                if (lane < 4) {
                    const unsigned* fp = &g_flag[g][(w * 4 + lane) * 8];
                    unsigned target = fb + (unsigned)l;
                    while ((int)(acqload(fp) - target) < 0) {}
                }
                __syncwarp();
            }
            // stage this warp's A slice: 32 rows x 128 k fp16
#pragma unroll
            for (int it = 0; it < 16; ++it) {
                int row = it * 2 + stRow;
                *(uint4*)(sA + row * PA + kw + stCh) =
                    ldcg4(&g_hf[c][(gbase + row) * Hn + kw + stCh]);
            }
            if (l < Ln && tid < BG) sX[tid] = __ldg(&x[(gbase + tid) * Ln + l]);
            __syncwarp();

            float acc[2][4][4];
#pragma unroll
            for (int mt = 0; mt < 2; ++mt)
#pragma unroll
                for (int nb = 0; nb < 4; ++nb)
#pragma unroll
                    for (int q = 0; q < 4; ++q) acc[mt][nb][q] = 0.f;

#pragma unroll
            for (int mt = 0; mt < 2; ++mt) {
                const uint32_t mo = (uint32_t)(mt * A_MT);
#pragma unroll
                for (int ks = 0; ks < 8; ++ks) {
                    uint32_t a0, a1, a2, a3;
                    LDSM4(a0, a1, a2, a3, aAddr + mo + ks * 32);
#pragma unroll
                    for (int nb = 0; nb < 4; ++nb) {
                        MMAF16(acc[mt][nb], a0, a1, a2, a3, Bh[ks][nb][0], Bh[ks][nb][1]);
                        MMAF16(acc[mt][nb], a0, a1, a2, a3, Bl[ks][nb][0], Bl[ks][nb][1]);
                    }
                }
            }
            float* rp = sRed + w * 32 * PN;
#pragma unroll
            for (int mt = 0; mt < 2; ++mt)
#pragma unroll
                for (int nb = 0; nb < 4; ++nb) {
                    int r0 = mt * 16 + gq, col = nb * 8 + tg * 2;
                    *(float2*)(rp + r0 * PN + col)       = make_float2(acc[mt][nb][0], acc[mt][nb][1]);
                    *(float2*)(rp + (r0 + 8) * PN + col) = make_float2(acc[mt][nb][2], acc[mt][nb][3]);
                }
        }
        __syncthreads();   // (a) partials ready; also: all warps done READING h_l

        // logits CTA publishes "h_l consumed"
        if (!isProd && tid == 0)
            relstore(&g_flagL[g * 8], fbL + (unsigned)l + 1u);

        if (act) {
            // reduce 8 k-slices: thread owns row m, cols n0..n0+3
            const int m = tid >> 3, n0 = (tid & 7) * 4;
            float4 s = *(const float4*)(sRed + m * PN + n0);
#pragma unroll
            for (int j = 1; j < 8; ++j) {
                float4 p = *(const float4*)(sRed + j * 32 * PN + m * PN + n0);
                s.x += p.x; s.y += p.y; s.z += p.z; s.w += p.w;
            }
            if (isProd) {
                if (l < Ln) {
                    // WAR guard: logits CTA must be done reading h_{l-1}
                    if (l > 0) {
                        const unsigned* fp = &g_flagL[g * 8];
                        unsigned target = fbL + (unsigned)l;
                        while ((int)(acqload(fp) - target) < 0) {}
                    }
                    const int xv = sX[m];
                    float4 Pv = *(const float4*)(&g_P[xv * Hn + ncol0 + n0]);
                    float h0 = fast_tanh(s.x + Pv.x), h1 = fast_tanh(s.y + Pv.y);
                    float h2 = fast_tanh(s.z + Pv.z), h3 = fast_tanh(s.w + Pv.w);
                    unsigned short u0 = __half_as_ushort(__float2half_rn(h0));
                    unsigned short u1 = __half_as_ushort(__float2half_rn(h1));
                    unsigned short u2 = __half_as_ushort(__float2half_rn(h2));
                    unsigned short u3 = __half_as_ushort(__float2half_rn(h3));
                    int i0 = (gbase + m) * Hn + ncol0 + n0;
                    *(uint2*)(&g_hf[1 - c][i0]) =
                        make_uint2(u0 | (u1 << 16), u2 | (u3 << 16));
                    if (l == Ln - 1)
                        *(float4*)(&outh[i0]) = make_float4(h0, h1, h2, h3);
                }
            } else if (l > 0) {
                float4 B0 = *(const float4*)(&bo[n0]);
                *(float4*)(&logits[((size_t)(gbase + m) * Ln + (l - 1)) * Vn + n0]) =
                    make_float4(s.x + B0.x, s.y + B0.y, s.z + B0.z, s.w + B0.w);
            }
        }
        __syncthreads();   // (b) h stores complete

        if (isProd && l < Ln && tid == 0)
            relstore(&g_flag[g][ntl * 8], fbSelf + (unsigned)l + 1u);
    }
}

extern "C" void kernel_launch(void* const* d_in, const int* in_sizes, int n_in,
                              void* d_out, int out_size) {
    const int*   x      = (const int*)d_in[0];
    const float* hidden = (const float*)d_in[1];
    const float* emb    = (const float*)d_in[2];
    const float* We     = (const float*)d_in[3];
    const float* Wh     = (const float*)d_in[4];
    const float* bh     = (const float*)d_in[5];
    const float* Wo     = (const float*)d_in[6];
    const float* bo     = (const float*)d_in[7];

    float* logits = (float*)d_out;
    float* outh   = logits + (size_t)Bn * Ln * Vn;

    cudaFuncSetAttribute(rnn_all,
                         cudaFuncAttributeMaxDynamicSharedMemorySize, SMEM_BYTES);
    rnn_all<<<G, NT, SMEM_BYTES>>>(x, hidden, emb, We, Wh, bh, Wo, bo, logits, outh);
}

// round 15
// speedup vs baseline: 1.2944x; 1.0678x over previous
#include <cuda_runtime.h>
#include <cuda_fp16.h>
#include <stdint.h>
#include <math.h>

#define Bn 128
#define Ln 1024
#define Vn 32
#define En 256
#define Hn 1024
#define NTOT 1056        // Hn + Vn (W_o folded)

#define NG  4            // independent batch groups
#define BG  32           // batch rows per group
#define NTL 33           // CTAs per group (32 h-producers + 1 logits tile)
#define NSL 32           // N cols per CTA
#define G   (NG * NTL)   // 132 persistent CTAs
#define NT  256          // 8 warps (one per k-slice)
#define KW  128          // K columns per warp
#define PA  1032         // A/B smem pitch (fp16): 2064B stride -> LDSM conflict-free
#define PN  36           // reduction pitch (floats)

// ---------------- device scratch ----------------
__device__ float    g_P[Vn * Hn];
__device__ __half   g_hf[3][Bn * Hn];       // fp16 hidden, TRIPLE-buffered
__device__ __half   g_WT_hi[NTOT * Hn];     // [n][k] fp16 hi
__device__ __half   g_WT_lo[NTOT * Hn];     // fp16 residual
__device__ unsigned g_cnt_all;              // prologue barrier (all G)
__device__ unsigned g_flag[NG][32 * 8];     // per-producer half-step flags (32B padded)
__device__ unsigned g_flagL[NG * 8];        // logits-CTA staging-done flags

// smem layout (bytes)
#define OFF_BLO 66048                       // (setup only) B-lo staging
#define OFF_RED 66048                       // steady state: reduction buffer
#define OFF_X   102912
#define SMEM_BYTES 132096
#define A_MT (16 * PA * 2)                  // byte offset between m-tiles

// ---------------- helpers ----------------
#define MMAF16(d, a0, a1, a2, a3, b0, b1) \
    asm volatile("mma.sync.aligned.m16n8k16.row.col.f32.f16.f16.f32 " \
        "{%0,%1,%2,%3}, {%4,%5,%6,%7}, {%8,%9}, {%0,%1,%2,%3};" \
        : "+f"((d)[0]), "+f"((d)[1]), "+f"((d)[2]), "+f"((d)[3]) \
        : "r"(a0), "r"(a1), "r"(a2), "r"(a3), "r"(b0), "r"(b1))

#define LDSM4(r0, r1, r2, r3, addr) \
    asm volatile("ldmatrix.sync.aligned.m8n8.x4.shared.b16 {%0,%1,%2,%3}, [%4];" \
        : "=r"(r0), "=r"(r1), "=r"(r2), "=r"(r3) : "r"(addr))

__device__ __forceinline__ uint32_t smem_u32(const void* p) {
    uint32_t a;
    asm("{ .reg .u64 t; cvta.to.shared.u64 t, %1; cvt.u32.u64 %0, t; }"
        : "=r"(a) : "l"(p));
    return a;
}
__device__ __forceinline__ unsigned acqload(const unsigned* p) {
    unsigned v;
    asm volatile("ld.acquire.gpu.u32 %0, [%1];" : "=r"(v) : "l"(p) : "memory");
    return v;
}
__device__ __forceinline__ void relstore(unsigned* p, unsigned v) {
    asm volatile("st.release.gpu.u32 [%0], %1;" :: "l"(p), "r"(v) : "memory");
}
__device__ __forceinline__ void arrive(unsigned* cnt) {
    asm volatile("red.release.gpu.global.add.u32 [%0], 1;" :: "l"(cnt) : "memory");
}
__device__ __forceinline__ void waitcnt(unsigned* cnt, unsigned target) {
    unsigned v = acqload(cnt);
    while ((int)(v - target) < 0) v = acqload(cnt);
}
__device__ __forceinline__ uint4 ldcg4(const void* p) {
    uint4 r;
    asm volatile("ld.global.cg.v4.u32 {%0,%1,%2,%3}, [%4];"
        : "=r"(r.x), "=r"(r.y), "=r"(r.z), "=r"(r.w) : "l"(p));
    return r;
}
__device__ __forceinline__ void pack_h16(float v, unsigned short& hi, unsigned short& lo) {
    __half hb = __float2half_rn(v);
    hi = __half_as_ushort(hb);
    lo = __half_as_ushort(__float2half_rn(v - __half2float(hb)));
}
__device__ __forceinline__ float fast_tanh(float x) {
    float e = __expf(2.0f * x);
    return 1.0f - __fdividef(2.0f, e + 1.0f);
}

// ---------------- the single persistent kernel ----------------
__global__ void __launch_bounds__(NT, 1)
rnn_all(const int* __restrict__ x, const float* __restrict__ hidden,
        const float* __restrict__ emb, const float* __restrict__ We,
        const float* __restrict__ Wh, const float* __restrict__ bh,
        const float* __restrict__ Wo, const float* __restrict__ bo,
        float* __restrict__ logits, float* __restrict__ outh) {
    extern __shared__ __align__(16) char dsm[];
    __half* sA   = (__half*)dsm;
    float*  sRed = (float*)(dsm + OFF_RED);
    int*    sX   = (int*)(dsm + OFF_X);

    const int tid = threadIdx.x, bid = blockIdx.x;
    const int g     = bid / NTL;        // batch group 0..3
    const int ntl   = bid % NTL;        // 0..32 (32 = logits tile)
    const bool isProd = (ntl < NTL - 1);
    const int gbase = g * BG;
    const int ncol0 = ntl * NSL;        // global N col base (1024 = logits)
    const int lane = tid & 31, w = tid >> 5;
    const int gq = lane >> 2, tg = lane & 3;
    const int kw = w * KW;              // this warp's k-slice base

    unsigned tokA = acqload(&g_cnt_all);
    unsigned fb = 0;
    if (lane < 4) fb = acqload(&g_flag[g][(w * 4 + lane) * 8]);
    unsigned fbSelf = 0;
    if (tid == 0 && isProd) fbSelf = acqload(&g_flag[g][ntl * 8]);
    const unsigned fbL = acqload(&g_flagL[g * 8]);

    // ======== prologue ========
    for (int k2 = tid; k2 < Hn; k2 += NT) {
#pragma unroll
        for (int j = 0; j < 8; ++j) {
            int n = bid * 8 + j;
            float wv = (n < Hn) ? Wh[k2 * Hn + n] : Wo[k2 * Vn + (n - Hn)];
            unsigned short hi, lo; pack_h16(wv, hi, lo);
            g_WT_hi[n * Hn + k2] = __ushort_as_half(hi);
            g_WT_lo[n * Hn + k2] = __ushort_as_half(lo);
        }
    }
    {
        int e = bid * NT + tid;
        if (e < Vn * Hn) {
            int v = e >> 10, h = e & 1023;
            float acc = bh[h];
            const float* er = emb + v * En;
#pragma unroll 8
            for (int q = 0; q < En; ++q) acc = fmaf(er[q], We[q * Hn + h], acc);
            g_P[e] = acc;
        }
    }
    if (bid < Bn) {
        int i0 = bid * Hn + tid * 4;
        float4 hv = *(const float4*)(hidden + i0);
        float vv[4] = {hv.x, hv.y, hv.z, hv.w};
        unsigned short uh[4], ul[4];
#pragma unroll
        for (int j = 0; j < 4; ++j) pack_h16(vv[j], uh[j], ul[j]);
        *(uint2*)(&g_hf[0][i0]) = make_uint2(uh[0] | (uh[1] << 16), uh[2] | (uh[3] << 16));
    }
    __syncthreads();
    if (tid == 0) arrive(&g_cnt_all);
    tokA += G;
    if (tid == 0) waitcnt(&g_cnt_all, tokA);
    __syncthreads();

    // ======== B setup: stage hi/lo tiles once, LDSM fragments into registers ========
    uint32_t Bh[8][4][2], Bl[8][4][2];
    {
        __half* sBlo = (__half*)(dsm + OFF_BLO);
#pragma unroll
        for (int it = 0; it < 16; ++it) {
            int i = (it * NT + tid) * 8;
            int n = i >> 10, k = i & 1023;
            *(uint4*)(sA + n * PA + k)   = *(const uint4*)(&g_WT_hi[(ncol0 + n) * Hn + k]);
            *(uint4*)(sBlo + n * PA + k) = *(const uint4*)(&g_WT_lo[(ncol0 + n) * Hn + k]);
        }
        __syncthreads();
        const uint32_t bBase = smem_u32(sA) +
            (uint32_t)(2 * ((lane & 7) * PA + kw + ((lane >> 3) & 1) * 8));
#pragma unroll
        for (int nb2 = 0; nb2 < 2; ++nb2) {
            const uint32_t ba = bBase + (uint32_t)(2 * (nb2 * 2 + (lane >> 4)) * 8 * PA);
#pragma unroll
            for (int ks = 0; ks < 8; ++ks) {
                LDSM4(Bh[ks][nb2 * 2][0], Bh[ks][nb2 * 2][1],
                      Bh[ks][nb2 * 2 + 1][0], Bh[ks][nb2 * 2 + 1][1], ba + ks * 32);
                LDSM4(Bl[ks][nb2 * 2][0], Bl[ks][nb2 * 2][1],
                      Bl[ks][nb2 * 2 + 1][0], Bl[ks][nb2 * 2 + 1][1],
                      ba + ks * 32 + (uint32_t)OFF_BLO);
            }
        }
        __syncthreads();
    }

    const uint32_t aAddr = smem_u32(sA) +
        (uint32_t)(2 * (((lane & 7) + ((lane >> 3) & 1) * 8) * PA + kw + (lane >> 4) * 8));
    const int stRow = lane >> 4;           // 0..1
    const int stCh  = (lane & 15) * 8;     // 0..120
    // reduce mapping: thread owns (row m within half, 2 cols)
    const int rm = tid >> 4;               // 0..15
    const int rn0 = (tid & 15) * 2;        // 0..30

    // ======== recurrence (half-tile pipelined dataflow) ========
    for (int l = 0; l <= Ln; ++l) {
        const int cRead  = l % 3;
        const int cWrite = (l + 1) % 3;
        const bool act = (l < Ln) || (!isProd);

        // ------------ HALF 0 (rows 0..15) ------------
        if (act) {
            if (l > 0) {
                if (lane < 4) {
                    const unsigned* fp = &g_flag[g][(w * 4 + lane) * 8];
                    unsigned target = fb + (unsigned)(2 * l - 1);
                    while ((int)(acqload(fp) - target) < 0) {}
                }
                __syncwarp();
            }
#pragma unroll
            for (int it = 0; it < 8; ++it) {
                int row = it * 2 + stRow;
                *(uint4*)(sA + row * PA + kw + stCh) =
                    ldcg4(&g_hf[cRead][(gbase + row) * Hn + kw + stCh]);
            }
            if (l < Ln && tid < BG) sX[tid] = __ldg(&x[(gbase + tid) * Ln + l]);
            __syncwarp();

            float acc[4][4];
#pragma unroll
            for (int nb = 0; nb < 4; ++nb)
#pragma unroll
                for (int q = 0; q < 4; ++q) acc[nb][q] = 0.f;
#pragma unroll
            for (int ks = 0; ks < 8; ++ks) {
                uint32_t a0, a1, a2, a3;
                LDSM4(a0, a1, a2, a3, aAddr + ks * 32);
#pragma unroll
                for (int nb = 0; nb < 4; ++nb) {
                    MMAF16(acc[nb], a0, a1, a2, a3, Bh[ks][nb][0], Bh[ks][nb][1]);
                    MMAF16(acc[nb], a0, a1, a2, a3, Bl[ks][nb][0], Bl[ks][nb][1]);
                }
            }
            float* rp = sRed + w * 32 * PN;
#pragma unroll
            for (int nb = 0; nb < 4; ++nb) {
                int r0 = gq, col = nb * 8 + tg * 2;
                *(float2*)(rp + r0 * PN + col)       = make_float2(acc[nb][0], acc[nb][1]);
                *(float2*)(rp + (r0 + 8) * PN + col) = make_float2(acc[nb][2], acc[nb][3]);
            }
        }
        __syncthreads();   // sync_a: half0 partials ready

        if (act) {
            float2 s = *(const float2*)(sRed + rm * PN + rn0);
#pragma unroll
            for (int j = 1; j < 8; ++j) {
                float2 p = *(const float2*)(sRed + j * 32 * PN + rm * PN + rn0);
                s.x += p.x; s.y += p.y;
            }
            if (isProd) {
                if (l < Ln) {
                    if (l > 1) {   // WAR: logits CTA done staging h_{l-2}
                        const unsigned* fp = &g_flagL[g * 8];
                        unsigned target = fbL + (unsigned)(l - 1);
                        while ((int)(acqload(fp) - target) < 0) {}
                    }
                    const int xv = sX[rm];
                    float2 Pv = *(const float2*)(&g_P[xv * Hn + ncol0 + rn0]);
                    float h0 = fast_tanh(s.x + Pv.x), h1 = fast_tanh(s.y + Pv.y);
                    unsigned short u0 = __half_as_ushort(__float2half_rn(h0));
                    unsigned short u1 = __half_as_ushort(__float2half_rn(h1));
                    int i0 = (gbase + rm) * Hn + ncol0 + rn0;
                    *(uint32_t*)(&g_hf[cWrite][i0]) = (uint32_t)u0 | ((uint32_t)u1 << 16);
                    if (l == Ln - 1) *(float2*)(&outh[i0]) = make_float2(h0, h1);
                }
            } else if (l > 0) {
                float2 B0 = *(const float2*)(&bo[rn0]);
                *(float2*)(&logits[((size_t)(gbase + rm) * Ln + (l - 1)) * Vn + rn0]) =
                    make_float2(s.x + B0.x, s.y + B0.y);
            }
        }
        __syncthreads();   // sync_b: half0 h stores done
        if (act && isProd && l < Ln && tid == 0)
            relstore(&g_flag[g][ntl * 8], fbSelf + (unsigned)(2 * l + 1));

        // ------------ HALF 1 (rows 16..31) ------------
        if (act) {
            if (l > 0) {
                if (lane < 4) {
                    const unsigned* fp = &g_flag[g][(w * 4 + lane) * 8];
                    unsigned target = fb + (unsigned)(2 * l);
                    while ((int)(acqload(fp) - target) < 0) {}
                }
                __syncwarp();
            }
#pragma unroll
            for (int it = 0; it < 8; ++it) {
                int row = 16 + it * 2 + stRow;
                *(uint4*)(sA + row * PA + kw + stCh) =
                    ldcg4(&g_hf[cRead][(gbase + row) * Hn + kw + stCh]);
            }
            __syncwarp();

            float acc[4][4];
#pragma unroll
            for (int nb = 0; nb < 4; ++nb)
#pragma unroll
                for (int q = 0; q < 4; ++q) acc[nb][q] = 0.f;
#pragma unroll
            for (int ks = 0; ks < 8; ++ks) {
                uint32_t a0, a1, a2, a3;
                LDSM4(a0, a1, a2, a3, aAddr + (uint32_t)A_MT + ks * 32);
#pragma unroll
                for (int nb = 0; nb < 4; ++nb) {
                    MMAF16(acc[nb], a0, a1, a2, a3, Bh[ks][nb][0], Bh[ks][nb][1]);
                    MMAF16(acc[nb], a0, a1, a2, a3, Bl[ks][nb][0], Bl[ks][nb][1]);
                }
            }
            float* rp = sRed + w * 32 * PN;
#pragma unroll
            for (int nb = 0; nb < 4; ++nb) {
                int r0 = 16 + gq, col = nb * 8 + tg * 2;
                *(float2*)(rp + r0 * PN + col)       = make_float2(acc[nb][0], acc[nb][1]);
                *(float2*)(rp + (r0 + 8) * PN + col) = make_float2(acc[nb][2], acc[nb][3]);
            }
        }
        __syncthreads();   // sync_c: half1 partials ready; staging of h_l complete
        if (!isProd && tid == 0)
            relstore(&g_flagL[g * 8], fbL + (unsigned)(l + 1));

        if (act) {
            const int m1 = 16 + rm;
            float2 s = *(const float2*)(sRed + m1 * PN + rn0);
#pragma unroll
            for (int j = 1; j < 8; ++j) {
                float2 p = *(const float2*)(sRed + j * 32 * PN + m1 * PN + rn0);
                s.x += p.x; s.y += p.y;
            }
            if (isProd) {
                if (l < Ln) {
                    const int xv = sX[m1];
                    float2 Pv = *(const float2*)(&g_P[xv * Hn + ncol0 + rn0]);
                    float h0 = fast_tanh(s.x + Pv.x), h1 = fast_tanh(s.y + Pv.y);
                    unsigned short u0 = __half_as_ushort(__float2half_rn(h0));
                    unsigned short u1 = __half_as_ushort(__float2half_rn(h1));
                    int i0 = (gbase + m1) * Hn + ncol0 + rn0;
                    *(uint32_t*)(&g_hf[cWrite][i0]) = (uint32_t)u0 | ((uint32_t)u1 << 16);
                    if (l == Ln - 1) *(float2*)(&outh[i0]) = make_float2(h0, h1);
                }
            } else if (l > 0) {
                float2 B0 = *(const float2*)(&bo[rn0]);
                *(float2*)(&logits[((size_t)(gbase + m1) * Ln + (l - 1)) * Vn + rn0]) =
                    make_float2(s.x + B0.x, s.y + B0.y);
            }
        }
        __syncthreads();   // sync_d: half1 h stores done
        if (act && isProd && l < Ln && tid == 0)
            relstore(&g_flag[g][ntl * 8], fbSelf + (unsigned)(2 * l + 2));
    }
}

extern "C" void kernel_launch(void* const* d_in, const int* in_sizes, int n_in,
                              void* d_out, int out_size) {
    const int*   x      = (const int*)d_in[0];
    const float* hidden = (const float*)d_in[1];
    const float* emb    = (const float*)d_in[2];
    const float* We     = (const float*)d_in[3];
    const float* Wh     = (const float*)d_in[4];
    const float* bh     = (const float*)d_in[5];
    const float* Wo     = (const float*)d_in[6];
    const float* bo     = (const float*)d_in[7];

    float* logits = (float*)d_out;
    float* outh   = logits + (size_t)Bn * Ln * Vn;

    cudaFuncSetAttribute(rnn_all,
                         cudaFuncAttributeMaxDynamicSharedMemorySize, SMEM_BYTES);
    rnn_all<<<G, NT, SMEM_BYTES>>>(x, hidden, emb, We, Wh, bh, Wo, bo, logits, outh);
}

// round 16
// speedup vs baseline: 1.4126x; 1.0913x over previous
#include <cuda_runtime.h>
#include <cuda_fp16.h>
#include <stdint.h>
#include <math.h>

#define Bn 128
#define Ln 1024
#define Vn 32
#define En 256
#define Hn 1024
#define NTOT 1056        // Hn + Vn (W_o folded)

#define NG  4            // independent batch groups
#define BG  32           // batch rows per group
#define NTL 33           // CTAs per group (32 h-producers + 1 logits tile)
#define NSL 32           // N cols per CTA
#define G   (NG * NTL)   // 132 persistent CTAs
#define NT  256          // 8 warps (one per k-slice)
#define KW  128          // K columns per warp
#define PA  1032         // B smem pitch (fp16), setup only
#define PN  36           // reduction pitch (floats)

// ---------------- device scratch ----------------
__device__ float    g_P[Vn * Hn];
// h in MMA-fragment layout: [c][g][half][kf][ks][lane] as uint4 (a0..a3)
// word index: ((((c*NG+g)*2+half)*8+kf)*8+ks)*32+lane  (uint4 granularity)
__device__ uint4    g_hfrag[3 * NG * 2 * 8 * 8 * 32];
__device__ __half   g_WT_hi[NTOT * Hn];     // [n][k] fp16 hi
__device__ __half   g_WT_lo[NTOT * Hn];     // fp16 residual
__device__ unsigned g_cnt_all;              // prologue barrier (all G)
__device__ unsigned g_flag[NG][32 * 8];     // per-producer half-step flags (32B padded)
__device__ unsigned g_flagL[NG * 8];        // logits-CTA read-done flags

#define FRAG_CSTride (NG * 2 * 8 * 8 * 32)  // uint4s per buffer

// smem layout (bytes)
#define OFF_BLO 66048                       // (setup only) B-lo staging
#define OFF_RED 66048                       // steady state: reduction buffer
#define OFF_X   102912
#define SMEM_BYTES 132096

// ---------------- helpers ----------------
#define MMAF16(d, a0, a1, a2, a3, b0, b1) \
    asm volatile("mma.sync.aligned.m16n8k16.row.col.f32.f16.f16.f32 " \
        "{%0,%1,%2,%3}, {%4,%5,%6,%7}, {%8,%9}, {%0,%1,%2,%3};" \
        : "+f"((d)[0]), "+f"((d)[1]), "+f"((d)[2]), "+f"((d)[3]) \
        : "r"(a0), "r"(a1), "r"(a2), "r"(a3), "r"(b0), "r"(b1))

#define LDSM4(r0, r1, r2, r3, addr) \
    asm volatile("ldmatrix.sync.aligned.m8n8.x4.shared.b16 {%0,%1,%2,%3}, [%4];" \
        : "=r"(r0), "=r"(r1), "=r"(r2), "=r"(r3) : "r"(addr))

__device__ __forceinline__ uint32_t smem_u32(const void* p) {
    uint32_t a;
    asm("{ .reg .u64 t; cvta.to.shared.u64 t, %1; cvt.u32.u64 %0, t; }"
        : "=r"(a) : "l"(p));
    return a;
}
__device__ __forceinline__ unsigned acqload(const unsigned* p) {
    unsigned v;
    asm volatile("ld.acquire.gpu.u32 %0, [%1];" : "=r"(v) : "l"(p) : "memory");
    return v;
}
__device__ __forceinline__ void relstore(unsigned* p, unsigned v) {
    asm volatile("st.release.gpu.u32 [%0], %1;" :: "l"(p), "r"(v) : "memory");
}
__device__ __forceinline__ void arrive(unsigned* cnt) {
    asm volatile("red.release.gpu.global.add.u32 [%0], 1;" :: "l"(cnt) : "memory");
}
__device__ __forceinline__ void waitcnt(unsigned* cnt, unsigned target) {
    unsigned v = acqload(cnt);
    while ((int)(v - target) < 0) v = acqload(cnt);
}
__device__ __forceinline__ uint4 ldcg4(const void* p) {
    uint4 r;
    asm volatile("ld.global.cg.v4.u32 {%0,%1,%2,%3}, [%4];"
        : "=r"(r.x), "=r"(r.y), "=r"(r.z), "=r"(r.w) : "l"(p));
    return r;
}
__device__ __forceinline__ void stcg32(void* p, uint32_t v) {
    asm volatile("st.global.cg.u32 [%0], %1;" :: "l"(p), "r"(v) : "memory");
}
__device__ __forceinline__ void pack_h16(float v, unsigned short& hi, unsigned short& lo) {
    __half hb = __float2half_rn(v);
    hi = __half_as_ushort(hb);
    lo = __half_as_ushort(__float2half_rn(v - __half2float(hb)));
}
__device__ __forceinline__ float fast_tanh(float x) {
    float e = __expf(2.0f * x);
    return 1.0f - __fdividef(2.0f, e + 1.0f);
}

// ---------------- the single persistent kernel ----------------
__global__ void __launch_bounds__(NT, 1)
rnn_all(const int* __restrict__ x, const float* __restrict__ hidden,
        const float* __restrict__ emb, const float* __restrict__ We,
        const float* __restrict__ Wh, const float* __restrict__ bh,
        const float* __restrict__ Wo, const float* __restrict__ bo,
        float* __restrict__ logits, float* __restrict__ outh) {
    extern __shared__ __align__(16) char dsm[];
    float* sRed = (float*)(dsm + OFF_RED);
    int*   sX   = (int*)(dsm + OFF_X);

    const int tid = threadIdx.x, bid = blockIdx.x;
    const int g     = bid / NTL;        // batch group 0..3
    const int ntl   = bid % NTL;        // 0..32 (32 = logits tile)
    const bool isProd = (ntl < NTL - 1);
    const int gbase = g * BG;
    const int ncol0 = ntl * NSL;        // global N col base (1024 = logits)
    const int lane = tid & 31, w = tid >> 5;
    const int gq = lane >> 2, tg = lane & 3;
    const int kw = w * KW;

    unsigned tokA = acqload(&g_cnt_all);
    unsigned fb = 0;
    if (lane < 4) fb = acqload(&g_flag[g][(w * 4 + lane) * 8]);
    unsigned fbSelf = 0;
    if (tid == 0 && isProd) fbSelf = acqload(&g_flag[g][ntl * 8]);
    const unsigned fbL = acqload(&g_flagL[g * 8]);

    // reduce/store mapping: thread owns (row rm within half, cols rn0..rn0+1)
    const int rm  = tid >> 4;              // 0..15
    const int rn0 = (tid & 15) * 2;        // 0..30
    // producer fragment-store decomposition for (rm, ncol0+rn0)
    const int kg   = ncol0 + rn0;          // global k-col (valid for producers)
    const int pkf  = kg >> 7;
    const int pks  = (kg >> 4) & 7;
    const int pcc  = kg & 15;
    const int plane = (rm & 7) * 4 + ((pcc & 7) >> 1);
    const int preg  = (rm >> 3) + 2 * (pcc >> 3);
    // word offsets within a buffer (uint32 granularity), halves 0/1
    const int wOff0 = ((((g * 2 + 0) * 8 + pkf) * 8 + pks) * 32 + plane) * 4 + preg;
    const int wOff1 = ((((g * 2 + 1) * 8 + pkf) * 8 + pks) * 32 + plane) * 4 + preg;
    uint32_t* fragW = (uint32_t*)g_hfrag;

    // consumer fragment load base (uint4 granularity), this warp's kf = w
    const int cBase0 = (((g * 2 + 0) * 8 + w) * 8) * 32 + lane;
    const int cBase1 = (((g * 2 + 1) * 8 + w) * 8) * 32 + lane;

    // ======== prologue ========
    for (int k2 = tid; k2 < Hn; k2 += NT) {
#pragma unroll
        for (int j = 0; j < 8; ++j) {
            int n = bid * 8 + j;
            float wv = (n < Hn) ? Wh[k2 * Hn + n] : Wo[k2 * Vn + (n - Hn)];
            unsigned short hi, lo; pack_h16(wv, hi, lo);
            g_WT_hi[n * Hn + k2] = __ushort_as_half(hi);
            g_WT_lo[n * Hn + k2] = __ushort_as_half(lo);
        }
    }
    {
        int e = bid * NT + tid;
        if (e < Vn * Hn) {
            int v = e >> 10, h = e & 1023;
            float acc = bh[h];
            const float* er = emb + v * En;
#pragma unroll 8
            for (int q = 0; q < En; ++q) acc = fmaf(er[q], We[q * Hn + h], acc);
            g_P[e] = acc;
        }
    }
    // h0 -> fragment layout (buffer 0); producers own their 32 cols
    if (isProd) {
#pragma unroll
        for (int hf = 0; hf < 2; ++hf) {
            int row = gbase + hf * 16 + rm;
            float v0 = hidden[row * Hn + kg];
            float v1 = hidden[row * Hn + kg + 1];
            unsigned short u0 = __half_as_ushort(__float2half_rn(v0));
            unsigned short u1 = __half_as_ushort(__float2half_rn(v1));
            fragW[(hf ? wOff1 : wOff0)] = (uint32_t)u0 | ((uint32_t)u1 << 16);
        }
    }
    __syncthreads();
    if (tid == 0) arrive(&g_cnt_all);
    tokA += G;
    if (tid == 0) waitcnt(&g_cnt_all, tokA);
    __syncthreads();

    // ======== B setup: stage hi/lo tiles once, LDSM fragments into registers ========
    uint32_t Bh[8][4][2], Bl[8][4][2];
    {
        __half* sBhi = (__half*)dsm;
        __half* sBlo = (__half*)(dsm + OFF_BLO);
#pragma unroll
        for (int it = 0; it < 16; ++it) {
            int i = (it * NT + tid) * 8;
            int n = i >> 10, k = i & 1023;
            *(uint4*)(sBhi + n * PA + k) = *(const uint4*)(&g_WT_hi[(ncol0 + n) * Hn + k]);
            *(uint4*)(sBlo + n * PA + k) = *(const uint4*)(&g_WT_lo[(ncol0 + n) * Hn + k]);
        }
        __syncthreads();
        const uint32_t bBase = smem_u32(sBhi) +
            (uint32_t)(2 * ((lane & 7) * PA + kw + ((lane >> 3) & 1) * 8));
#pragma unroll
        for (int nb2 = 0; nb2 < 2; ++nb2) {
            const uint32_t ba = bBase + (uint32_t)(2 * (nb2 * 2 + (lane >> 4)) * 8 * PA);
#pragma unroll
            for (int ks = 0; ks < 8; ++ks) {
                LDSM4(Bh[ks][nb2 * 2][0], Bh[ks][nb2 * 2][1],
                      Bh[ks][nb2 * 2 + 1][0], Bh[ks][nb2 * 2 + 1][1], ba + ks * 32);
                LDSM4(Bl[ks][nb2 * 2][0], Bl[ks][nb2 * 2][1],
                      Bl[ks][nb2 * 2 + 1][0], Bl[ks][nb2 * 2 + 1][1],
                      ba + ks * 32 + (uint32_t)OFF_BLO);
            }
        }
        __syncthreads();
    }

    // ======== recurrence (fragment-direct, half-tile pipelined) ========
    for (int l = 0; l <= Ln; ++l) {
        const int cRead  = l % 3;
        const int cWrite = (l + 1) % 3;
        const bool act = (l < Ln) || (!isProd);
        const uint4* frR = g_hfrag + cRead * FRAG_CSTride;
        uint32_t* frW = fragW + cWrite * (FRAG_CSTride * 4);

        // ------------ HALF 0 (rows 0..15) ------------
        if (act) {
            if (l > 0) {
                if (lane < 4) {
                    const unsigned* fp = &g_flag[g][(w * 4 + lane) * 8];
                    unsigned target = fb + (unsigned)(2 * l - 1);
                    while ((int)(acqload(fp) - target) < 0) {}
                }
                __syncwarp();
            }
            uint4 A0[8];
#pragma unroll
            for (int ks = 0; ks < 8; ++ks)
                A0[ks] = ldcg4(&frR[cBase0 + ks * 32]);
            if (l < Ln && tid < BG) sX[tid] = __ldg(&x[(gbase + tid) * Ln + l]);

            float acc[4][4];
#pragma unroll
            for (int nb = 0; nb < 4; ++nb)
#pragma unroll
                for (int q = 0; q < 4; ++q) acc[nb][q] = 0.f;
#pragma unroll
            for (int ks = 0; ks < 8; ++ks) {
#pragma unroll
                for (int nb = 0; nb < 4; ++nb) {
                    MMAF16(acc[nb], A0[ks].x, A0[ks].y, A0[ks].z, A0[ks].w,
                           Bh[ks][nb][0], Bh[ks][nb][1]);
                    MMAF16(acc[nb], A0[ks].x, A0[ks].y, A0[ks].z, A0[ks].w,
                           Bl[ks][nb][0], Bl[ks][nb][1]);
                }
            }
            float* rp = sRed + w * 32 * PN;
#pragma unroll
            for (int nb = 0; nb < 4; ++nb) {
                int col = nb * 8 + tg * 2;
                *(float2*)(rp + gq * PN + col)       = make_float2(acc[nb][0], acc[nb][1]);
                *(float2*)(rp + (gq + 8) * PN + col) = make_float2(acc[nb][2], acc[nb][3]);
            }
        }
        __syncthreads();   // sync_a

        if (act) {
            float2 s = *(const float2*)(sRed + rm * PN + rn0);
#pragma unroll
            for (int j = 1; j < 8; ++j) {
                float2 p = *(const float2*)(sRed + j * 32 * PN + rm * PN + rn0);
                s.x += p.x; s.y += p.y;
            }
            if (isProd) {
                if (l < Ln) {
                    if (l > 1) {   // WAR: logits CTA done reading h_{l-2}
                        const unsigned* fp = &g_flagL[g * 8];
                        unsigned target = fbL + (unsigned)(l - 1);
                        while ((int)(acqload(fp) - target) < 0) {}
                    }
                    const int xv = sX[rm];
                    float2 Pv = *(const float2*)(&g_P[xv * Hn + kg]);
                    float h0 = fast_tanh(s.x + Pv.x), h1 = fast_tanh(s.y + Pv.y);
                    unsigned short u0 = __half_as_ushort(__float2half_rn(h0));
                    unsigned short u1 = __half_as_ushort(__float2half_rn(h1));
                    stcg32(&frW[wOff0], (uint32_t)u0 | ((uint32_t)u1 << 16));
                    if (l == Ln - 1)
                        *(float2*)(&outh[(gbase + rm) * Hn + kg]) = make_float2(h0, h1);
                }
            } else if (l > 0) {
                float2 B0 = *(const float2*)(&bo[rn0]);
                *(float2*)(&logits[((size_t)(gbase + rm) * Ln + (l - 1)) * Vn + rn0]) =
                    make_float2(s.x + B0.x, s.y + B0.y);
            }
        }
        __syncthreads();   // sync_b
        if (act && isProd && l < Ln && tid == 0)
            relstore(&g_flag[g][ntl * 8], fbSelf + (unsigned)(2 * l + 1));

        // ------------ HALF 1 (rows 16..31) ------------
        if (act) {
            if (l > 0) {
                if (lane < 4) {
                    const unsigned* fp = &g_flag[g][(w * 4 + lane) * 8];
                    unsigned target = fb + (unsigned)(2 * l);
                    while ((int)(acqload(fp) - target) < 0) {}
                }
                __syncwarp();
            }
            uint4 A1[8];
#pragma unroll
            for (int ks = 0; ks < 8; ++ks)
                A1[ks] = ldcg4(&frR[cBase1 + ks * 32]);

            float acc[4][4];
#pragma unroll
            for (int nb = 0; nb < 4; ++nb)
#pragma unroll
                for (int q = 0; q < 4; ++q) acc[nb][q] = 0.f;
#pragma unroll
            for (int ks = 0; ks < 8; ++ks) {
#pragma unroll
                for (int nb = 0; nb < 4; ++nb) {
                    MMAF16(acc[nb], A1[ks].x, A1[ks].y, A1[ks].z, A1[ks].w,
                           Bh[ks][nb][0], Bh[ks][nb][1]);
                    MMAF16(acc[nb], A1[ks].x, A1[ks].y, A1[ks].z, A1[ks].w,
                           Bl[ks][nb][0], Bl[ks][nb][1]);
                }
            }
            float* rp = sRed + w * 32 * PN;
#pragma unroll
            for (int nb = 0; nb < 4; ++nb) {
                int col = nb * 8 + tg * 2;
                *(float2*)(rp + (16 + gq) * PN + col)  = make_float2(acc[nb][0], acc[nb][1]);
                *(float2*)(rp + (24 + gq) * PN + col)  = make_float2(acc[nb][2], acc[nb][3]);
            }
        }
        __syncthreads();   // sync_c: half1 partials ready; all reads of h_l done
        if (!isProd && tid == 0)
            relstore(&g_flagL[g * 8], fbL + (unsigned)(l + 1));

        if (act) {
            const int m1 = 16 + rm;
            float2 s = *(const float2*)(sRed + m1 * PN + rn0);
#pragma unroll
            for (int j = 1; j < 8; ++j) {
                float2 p = *(const float2*)(sRed + j * 32 * PN + m1 * PN + rn0);
                s.x += p.x; s.y += p.y;
            }
            if (isProd) {
                if (l < Ln) {
                    const int xv = sX[m1];
                    float2 Pv = *(const float2*)(&g_P[xv * Hn + kg]);
                    float h0 = fast_tanh(s.x + Pv.x), h1 = fast_tanh(s.y + Pv.y);
                    unsigned short u0 = __half_as_ushort(__float2half_rn(h0));
                    unsigned short u1 = __half_as_ushort(__float2half_rn(h1));
                    stcg32(&frW[wOff1], (uint32_t)u0 | ((uint32_t)u1 << 16));
                    if (l == Ln - 1)
                        *(float2*)(&outh[(gbase + m1) * Hn + kg]) = make_float2(h0, h1);
                }
            } else if (l > 0) {
                float2 B0 = *(const float2*)(&bo[rn0]);
                *(float2*)(&logits[((size_t)(gbase + m1) * Ln + (l - 1)) * Vn + rn0]) =
                    make_float2(s.x + B0.x, s.y + B0.y);
            }
        }
        __syncthreads();   // sync_d
        if (act && isProd && l < Ln && tid == 0)
            relstore(&g_flag[g][ntl * 8], fbSelf + (unsigned)(2 * l + 2));
    }
}

extern "C" void kernel_launch(void* const* d_in, const int* in_sizes, int n_in,
                              void* d_out, int out_size) {
    const int*   x      = (const int*)d_in[0];
    const float* hidden = (const float*)d_in[1];
    const float* emb    = (const float*)d_in[2];
    const float* We     = (const float*)d_in[3];
    const float* Wh     = (const float*)d_in[4];
    const float* bh     = (const float*)d_in[5];
    const float* Wo     = (const float*)d_in[6];
    const float* bo     = (const float*)d_in[7];

    float* logits = (float*)d_out;
    float* outh   = logits + (size_t)Bn * Ln * Vn;

    cudaFuncSetAttribute(rnn_all,
                         cudaFuncAttributeMaxDynamicSharedMemorySize, SMEM_BYTES);
    rnn_all<<<G, NT, SMEM_BYTES>>>(x, hidden, emb, We, Wh, bh, Wo, bo, logits, outh);
}